// round 14
// baseline (speedup 1.0000x reference)
#include <cuda_runtime.h>
#include <cuda_bf16.h>

// DinoPool == masked average pooling of x over 512-row blocks.
// x: [B=4, S=4096, C=384] fp32 -> out same shape.
//
// R14: R6 structure with Blackwell 256-bit memory ops. 384 CTAs x 256 thr,
// unit = (bat, blk, 32-float chunk = 128B/row). Each thread owns a 32B
// (8-float) column group and 8 rows: 8x ld.global.nc.v8 + 8x st.global.v8.
// Warp access = 8 rows x 128B full lines. Halves L2 write-request count
// (1.57M -> 787K) to test whether the ~3.1TB/s write cap is request-rate
// limited rather than byte limited.

static constexpr int S     = 4096;
static constexpr int C     = 384;
static constexpr int BLOCK = 512;
static constexpr int NT    = 256;
static constexpr int NCHK  = 12;     // 12 chunks of 32 floats (128B) per row
static constexpr int RG    = 64;     // rowgroups (t>>2)
static constexpr int RPT   = BLOCK / RG;   // 8 rows per thread

__device__ __forceinline__ void ldg_v8(const float* p, float* r) {
    asm volatile("ld.global.nc.v8.f32 {%0,%1,%2,%3,%4,%5,%6,%7}, [%8];"
                 : "=f"(r[0]), "=f"(r[1]), "=f"(r[2]), "=f"(r[3]),
                   "=f"(r[4]), "=f"(r[5]), "=f"(r[6]), "=f"(r[7])
                 : "l"(p));
}

__device__ __forceinline__ void stg_v8(float* p, const float* r) {
    asm volatile("st.global.v8.f32 [%0], {%1,%2,%3,%4,%5,%6,%7,%8};"
                 :: "l"(p),
                    "f"(r[0]), "f"(r[1]), "f"(r[2]), "f"(r[3]),
                    "f"(r[4]), "f"(r[5]), "f"(r[6]), "f"(r[7])
                 : "memory");
}

__global__ __launch_bounds__(NT, 8)
void dinopool_kernel(const float* __restrict__ x, float* __restrict__ out) {
    const int chunk = blockIdx.x;   // 0..11
    const int blk   = blockIdx.y;   // 0..7
    const int bat   = blockIdx.z;   // 0..3

    const int c8 = threadIdx.x & 3;    // 32B group within the 128B chunk
    const int rg = threadIdx.x >> 2;   // 0..63

    // float index of (row rg*RPT, this 8-float group)
    const size_t baseF = ((size_t)bat * S + (size_t)blk * BLOCK
                          + (size_t)rg * RPT) * C
                         + (size_t)chunk * 32 + (size_t)c8 * 8;

    // ---- 8 independent 32B loads per thread ----
    float acc[8] = {0.f, 0.f, 0.f, 0.f, 0.f, 0.f, 0.f, 0.f};
    #pragma unroll
    for (int r = 0; r < RPT; r++) {
        float v[8];
        ldg_v8(x + baseF + (size_t)r * C, v);
        #pragma unroll
        for (int i = 0; i < 8; i++) acc[i] += v[i];
    }

    // ---- tree reduction across 64 rowgroups in smem ----
    __shared__ float sm[RG][4][8];      // 8KB
    #pragma unroll
    for (int i = 0; i < 8; i++) sm[rg][c8][i] = acc[i];
    __syncthreads();
    #pragma unroll
    for (int s = RG / 2; s >= 1; s >>= 1) {
        if (rg < s) {
            #pragma unroll
            for (int i = 0; i < 8; i++)
                sm[rg][c8][i] += sm[rg + s][c8][i];
        }
        __syncthreads();
    }

    // ---- scale to mean (threads rg==0), then broadcast ----
    if (rg == 0) {
        const float inv = 1.0f / (float)BLOCK;
        #pragma unroll
        for (int i = 0; i < 8; i++) sm[0][c8][i] *= inv;
    }
    __syncthreads();

    float mean[8];
    #pragma unroll
    for (int i = 0; i < 8; i++) mean[i] = sm[0][c8][i];

    // ---- 8 x 32B stores per thread: full 128B lines per warp row ----
    #pragma unroll
    for (int r = 0; r < RPT; r++) {
        stg_v8(out + baseF + (size_t)r * C, mean);
    }
}

extern "C" void kernel_launch(void* const* d_in, const int* in_sizes, int n_in,
                              void* d_out, int out_size) {
    const float* x = (const float*)d_in[0];   // [4, 4096, 384] fp32
    float* out     = (float*)d_out;
    (void)in_sizes; (void)n_in; (void)out_size;

    dim3 grid(NCHK /*12*/, S / BLOCK /*8*/, 4 /*batch*/);   // 384 CTAs
    dinopool_kernel<<<grid, NT>>>(x, out);
}

// round 15
// speedup vs baseline: 1.1633x; 1.1633x over previous
#include <cuda_runtime.h>
#include <cuda_bf16.h>

// DinoPool == masked average pooling of x over 512-row blocks.
// x: [B=4, S=4096, C=384] fp32 -> out same shape.
// out[b, s, c] = mean_{r in block(s)} x[b, r, c].
//
// R15: R6 structure (best: 384 CTAs x 256 thr, unit = (bat,blk,8-float4-col
// chunk), full-128B-line warp accesses) with max read MLP: launch_bounds
// (256,3) gives ~85 regs so ALL 16 LDG.128 front-issue from one base reg
// with immediate offsets before any FADD; pairwise-tree accumulate.
// Goal: raise the DRAM read rate (5.1 -> ~6.5+ TB/s) to shrink the
// unhidden read prefix ahead of the hard ~8.1us write stream.

static constexpr int S       = 4096;
static constexpr int C       = 384;
static constexpr int C4      = C / 4;      // 96 float4 per row
static constexpr int BLOCK   = 512;
static constexpr int NBLK    = 8;
static constexpr int NBAT    = 4;
static constexpr int CH4     = 8;          // float4 columns per CTA (128B)
static constexpr int NCH     = C4 / CH4;   // 12 chunks
static constexpr int NT      = 256;
static constexpr int RG      = NT / CH4;   // 32 rowgroups
static constexpr int RPT     = BLOCK / RG; // 16 rows per thread

__global__ __launch_bounds__(NT, 3)
void dinopool_kernel(const float* __restrict__ x, float* __restrict__ out) {
    const int chunk = blockIdx.x;   // 0..11
    const int blk   = blockIdx.y;   // 0..7
    const int bat   = blockIdx.z;   // 0..3

    const int col = threadIdx.x & (CH4 - 1);   // 0..7
    const int rg  = threadIdx.x >> 3;          // 0..31

    const float4* __restrict__ x4 = reinterpret_cast<const float4*>(x);
    float4* __restrict__ o4       = reinterpret_cast<float4*>(out);

    // float4 index of (row rg*RPT, this column) within this (bat, blk)
    const size_t base = ((size_t)bat * S + (size_t)blk * BLOCK
                         + (size_t)rg * RPT) * C4
                        + (size_t)chunk * CH4 + col;

    // ---- issue ALL 16 loads before any arithmetic (max MLP) ----
    float4 v[RPT];
    #pragma unroll
    for (int r = 0; r < RPT; r++) {
        v[r] = __ldg(&x4[base + (size_t)r * C4]);
    }

    // ---- pairwise tree accumulation (short dependency chains) ----
    #pragma unroll
    for (int stride = 1; stride < RPT; stride <<= 1) {
        #pragma unroll
        for (int i = 0; i < RPT; i += 2 * stride) {
            v[i].x += v[i + stride].x;
            v[i].y += v[i + stride].y;
            v[i].z += v[i + stride].z;
            v[i].w += v[i + stride].w;
        }
    }
    float4 acc = v[0];

    // ---- tree reduction across 32 rowgroups in smem ----
    __shared__ float4 sm[RG][CH4];
    sm[rg][col] = acc;
    __syncthreads();
    #pragma unroll
    for (int s = RG / 2; s >= 1; s >>= 1) {
        if (rg < s) {
            float4 a = sm[rg][col];
            float4 b = sm[rg + s][col];
            a.x += b.x; a.y += b.y; a.z += b.z; a.w += b.w;
            sm[rg][col] = a;
        }
        __syncthreads();
    }

    // ---- broadcast mean to this CTA's 512 output rows ----
    float4 mean = sm[0][col];
    const float inv = 1.0f / (float)BLOCK;
    mean.x *= inv; mean.y *= inv; mean.z *= inv; mean.w *= inv;

    #pragma unroll
    for (int r = 0; r < RPT; r++) {
        o4[base + (size_t)r * C4] = mean;
    }
}

extern "C" void kernel_launch(void* const* d_in, const int* in_sizes, int n_in,
                              void* d_out, int out_size) {
    const float* x = (const float*)d_in[0];   // [4, 4096, 384] fp32
    float* out     = (float*)d_out;
    (void)in_sizes; (void)n_in; (void)out_size;

    dim3 grid(NCH /*12*/, NBLK /*8*/, NBAT /*4*/);   // 384 CTAs
    dinopool_kernel<<<grid, NT>>>(x, out);
}

// round 16
// speedup vs baseline: 1.1875x; 1.0208x over previous
#include <cuda_runtime.h>
#include <cuda_bf16.h>

// DinoPool == masked average pooling of x over 512-row blocks.
// x: [B=4, S=4096, C=384] fp32 -> out same shape.
// out[b, s, c] = mean_{r in block(s)} x[b, r, c].
//
// R16 == R6 champion, re-validated (10.53us best). 384 CTAs x 256 thr,
// full 148-SM coverage; unit = (bat, blk, 8-float4-col chunk); every warp
// access (load and store) is a full 128B L2 line; 16 independent loads per
// thread cover DRAM latency; smem tree reduction; broadcast stores.
// 15 rounds of structural/policy exploration established:
//   read cap ~5.1 TB/s (DRAM), write cap ~3.1 TB/s (fabric-side,
//   granularity/policy-independent), partial overlap via CTA spread.
// This shape sits at that floor: ~2.4us exposed read + ~8.1us write stream.

static constexpr int S       = 4096;
static constexpr int C       = 384;    // H*D
static constexpr int C4      = C / 4;  // 96 float4 per row
static constexpr int BLOCK   = 512;
static constexpr int NBLK    = 8;
static constexpr int NBAT    = 4;
static constexpr int CH4     = 8;          // float4 columns per CTA (128B)
static constexpr int NCH     = C4 / CH4;   // 12 chunks
static constexpr int NT      = 256;
static constexpr int RG      = NT / CH4;   // 32 rowgroups
static constexpr int RPT     = BLOCK / RG; // 16 rows per thread

__global__ __launch_bounds__(NT, 4)
void dinopool_kernel(const float* __restrict__ x, float* __restrict__ out) {
    const int chunk = blockIdx.x;   // 0..11
    const int blk   = blockIdx.y;   // 0..7
    const int bat   = blockIdx.z;   // 0..3

    const int col = threadIdx.x & (CH4 - 1);   // 0..7
    const int rg  = threadIdx.x >> 3;          // 0..31

    const float4* __restrict__ x4 = reinterpret_cast<const float4*>(x);
    float4* __restrict__ o4       = reinterpret_cast<float4*>(out);

    // float4 index of (row rg*RPT, this column) within this (bat, blk)
    const size_t base = ((size_t)bat * S + (size_t)blk * BLOCK
                         + (size_t)rg * RPT) * C4
                        + (size_t)chunk * CH4 + col;

    // ---- accumulate 16 rows per thread (independent loads, high MLP) ----
    float4 acc = make_float4(0.f, 0.f, 0.f, 0.f);
    #pragma unroll
    for (int r = 0; r < RPT; r++) {
        float4 v = __ldcs(&x4[base + (size_t)r * C4]);
        acc.x += v.x; acc.y += v.y; acc.z += v.z; acc.w += v.w;
    }

    // ---- tree reduction across 32 rowgroups in smem ----
    __shared__ float4 sm[RG][CH4];
    sm[rg][col] = acc;
    __syncthreads();
    #pragma unroll
    for (int s = RG / 2; s >= 1; s >>= 1) {
        if (rg < s) {
            float4 a = sm[rg][col];
            float4 b = sm[rg + s][col];
            a.x += b.x; a.y += b.y; a.z += b.z; a.w += b.w;
            sm[rg][col] = a;
        }
        __syncthreads();
    }

    // ---- broadcast mean to this CTA's 512 output rows ----
    float4 mean = sm[0][col];
    const float inv = 1.0f / (float)BLOCK;
    mean.x *= inv; mean.y *= inv; mean.z *= inv; mean.w *= inv;

    #pragma unroll
    for (int r = 0; r < RPT; r++) {
        o4[base + (size_t)r * C4] = mean;
    }
}

extern "C" void kernel_launch(void* const* d_in, const int* in_sizes, int n_in,
                              void* d_out, int out_size) {
    const float* x = (const float*)d_in[0];   // [4, 4096, 384] fp32
    float* out     = (float*)d_out;
    (void)in_sizes; (void)n_in; (void)out_size;

    dim3 grid(NCH /*12*/, NBLK /*8*/, NBAT /*4*/);   // 384 CTAs
    dinopool_kernel<<<grid, NT>>>(x, out);
}